// round 9
// baseline (speedup 1.0000x reference)
#include <cuda_runtime.h>
#include <math_constants.h>

// Problem constants
#define N_BATCH 4
#define C_CH    128
#define S_FR    31
#define HW      704           // 32*22
#define NS      120           // 4*(31-1)
#define NPIX    87296         // 4*31*704 (= 64*1364)
#define TOPK    16
#define NB      32            // denominator bins (= warp size)
#define NWARP   22            // 704/32
#define LOG2E   1.4426950408889634f
#define LN2F    0.6931471805599453f

// Scratch (device globals — no allocation allowed)
__device__ float g_X0[NS * HW];        // a values
__device__ float g_BL[NS * HW];        // b * log2e (order-preserving)

__device__ __forceinline__ float ex2(float x) {
    float r;
    asm("ex2.approx.f32 %0, %1;" : "=f"(r) : "f"(x));
    return r;
}

// ---------------------------------------------------------------------------
// Kernel A (R3 winner, verbatim): channel contraction, 2 threads per pixel.
// ---------------------------------------------------------------------------
__global__ void kA(const float* __restrict__ x,
                   const float* __restrict__ w1, const float* __restrict__ b1,
                   const float* __restrict__ w2, const float* __restrict__ b2) {
    __shared__ float sw1[C_CH], sw2[C_CH];
    __shared__ float r1s[64], r2s[64];
    int tid = threadIdx.x;          // 0..127
    sw1[tid] = w1[tid];
    sw2[tid] = w2[tid];
    __syncthreads();

    int half = tid >> 6;            // 0 or 1
    int px   = tid & 63;
    int p = blockIdx.x * 64 + px;   // NPIX = 64*1364 exactly
    int n = p / (S_FR * HW);
    int q = p - n * (S_FR * HW);
    int f = q / HW;
    int i = q - f * HW;

    const float* xp = x + (size_t)n * (C_CH * S_FR * HW)
                        + (size_t)(half * 64) * (S_FR * HW) + q;
    const float* pw1 = sw1 + half * 64;
    const float* pw2 = sw2 + half * 64;

    float y1a = 0.f, y1b = 0.f, y2a = 0.f, y2b = 0.f;
#pragma unroll
    for (int cb = 0; cb < 64; cb += 16) {
        float v[16];
#pragma unroll
        for (int u = 0; u < 16; u++) v[u] = xp[(cb + u) * (S_FR * HW)];
#pragma unroll
        for (int u = 0; u < 16; u += 2) {
            y1a = fmaf(v[u],     pw1[cb + u],     y1a);
            y2a = fmaf(v[u],     pw2[cb + u],     y2a);
            y1b = fmaf(v[u + 1], pw1[cb + u + 1], y1b);
            y2b = fmaf(v[u + 1], pw2[cb + u + 1], y2b);
        }
    }
    float y1 = y1a + y1b, y2 = y2a + y2b;

    if (half == 1) { r1s[px] = y1; r2s[px] = y2; }
    __syncthreads();
    if (half == 0) {
        y1 += r1s[px];
        y2 += r2s[px];
        if (f < S_FR - 1) g_X0[(n * (S_FR - 1) + f) * HW + i] = y1 + b1[0];
        if (f >= 1)       g_BL[(n * (S_FR - 1) + f - 1) * HW + i] = (y2 + b2[0]) * LOG2E;
    }
}

// ---------------------------------------------------------------------------
// Fused kernel BC. One block per row, 704 threads.
// NB=32 bins. Denominator: warp-UNIFORM ascending bin traversal (LDS
// broadcast) with exact ex2 refresh every 8 bins. Selection: histogram
// threshold + candidate gather + warp bitonic (fallback: iterative).
// ---------------------------------------------------------------------------
__global__ void __launch_bounds__(HW)
kBC(float* __restrict__ out) {
    __shared__ float  sv[HW], sv2[HW];          // fallback-only consumable copies
    __shared__ float4 sbin[NB];                 // (S0, S1, S2/2, S3/6)
    __shared__ float  rmin[NWARP], rmax[NWARP];
    __shared__ float  ssel[32];
    __shared__ float  s_lo, s_W;
    __shared__ int    s_ttop, s_tbot, s_fbtop, s_fbbot;
    __shared__ int    s_ctop, s_cbot;
    __shared__ float  candT[40], candB[40];

    int r = blockIdx.x;
    int tid = threadIdx.x;   // 0..703
    int lane = tid & 31, wid = tid >> 5;
    float* binsf = reinterpret_cast<float*>(sbin);

    float bv = g_BL[r * HW + tid];
    float a  = g_X0[r * HW + tid];
    sv[tid] = bv; sv2[tid] = bv;
    if (tid < NB) sbin[tid] = make_float4(0.f, 0.f, 0.f, 0.f);
    if (tid == HW - 1) { s_ctop = 0; s_cbot = 0; }

    // warp min/max -> block min/max
    float lmin = bv, lmax = bv;
#pragma unroll
    for (int o = 16; o; o >>= 1) {
        lmin = fminf(lmin, __shfl_xor_sync(0xffffffffu, lmin, o));
        lmax = fmaxf(lmax, __shfl_xor_sync(0xffffffffu, lmax, o));
    }
    if (lane == 0) { rmin[wid] = lmin; rmax[wid] = lmax; }
    __syncthreads();
    if (tid == 0) {
        float lo = rmin[0], hi = rmax[0];
#pragma unroll
        for (int w = 1; w < NWARP; w++) { lo = fminf(lo, rmin[w]); hi = fmaxf(hi, rmax[w]); }
        s_lo = lo;
        s_W  = (hi - lo) * (1.0f / NB) + 1e-30f;
    }
    __syncthreads();

    float lo = s_lo, W = s_W, invW = 1.0f / W;
    int m;
    {
        m = (int)((bv - lo) * invW);
        m = (m > NB - 1) ? NB - 1 : (m < 0 ? 0 : m);
        float d = bv - fmaf((float)m + 0.5f, W, lo);
        float* bp = binsf + 4 * m;
        atomicAdd(bp + 0, 1.0f);
        atomicAdd(bp + 1, d);
        atomicAdd(bp + 2, 0.5f * d * d);
        atomicAdd(bp + 3, (1.0f / 6.0f) * d * d * d);
    }
    __syncthreads();

    // thresholds: lane-per-bin scans (warps 0 and 1)
    if (wid == 0) {
        float c = binsf[lane * 4];
        float suf = c;
#pragma unroll
        for (int o = 1; o < 32; o <<= 1) {
            float v = __shfl_down_sync(0xffffffffu, suf, o);
            if (lane + o < 32) suf += v;
        }
        int best = (suf >= 16.f) ? lane : -1;
#pragma unroll
        for (int o = 16; o; o >>= 1)
            best = max(best, __shfl_xor_sync(0xffffffffu, best, o));
        float Sb = __shfl_sync(0xffffffffu, suf, best);
        if (lane == 0) { s_ttop = best; s_fbtop = (Sb > 32.f) ? 1 : 0; }
    } else if (wid == 1) {
        float c = binsf[lane * 4];
        float pre = c;
#pragma unroll
        for (int o = 1; o < 32; o <<= 1) {
            float v = __shfl_up_sync(0xffffffffu, pre, o);
            if (lane >= o) pre += v;
        }
        int best = (pre >= 16.f) ? lane : 32;
#pragma unroll
        for (int o = 16; o; o >>= 1)
            best = min(best, __shfl_xor_sync(0xffffffffu, best, o));
        float Pb = __shfl_sync(0xffffffffu, pre, best);
        if (lane == 0) { s_tbot = best; s_fbbot = (Pb > 32.f) ? 1 : 0; }
    }
    __syncthreads();

    // candidate gather (counts <= 32 when no fallback)
    if (!s_fbtop && m >= s_ttop) candT[atomicAdd(&s_ctop, 1)] = bv;
    if (!s_fbbot && m <= s_tbot) candB[atomicAdd(&s_cbot, 1)] = bv;
    __syncthreads();

    // selection: warp 0 top-16 desc, warp 1 bottom-16 asc
    if (wid == 0) {
        if (!s_fbtop) {
            float v = (lane < s_ctop) ? candT[lane] : -CUDART_INF_F;
#pragma unroll
            for (int k = 2; k <= 32; k <<= 1) {
#pragma unroll
                for (int j = k >> 1; j > 0; j >>= 1) {
                    float o = __shfl_xor_sync(0xffffffffu, v, j);
                    bool up = ((lane & k) == 0);
                    bool keepMin = (((lane & j) == 0) == up);
                    v = keepMin ? fminf(v, o) : fmaxf(v, o);
                }
            }
            if (lane >= 16) ssel[31 - lane] = v;   // ascending -> top-16 desc
        } else {
            for (int it = 0; it < TOPK; it++) {
                float lm = -CUDART_INF_F; int li = 0;
                for (int j = lane; j < HW; j += 32) {
                    float v = sv[j];
                    if (v > lm) { lm = v; li = j; }
                }
#pragma unroll
                for (int o = 16; o; o >>= 1) {
                    float ov = __shfl_xor_sync(0xffffffffu, lm, o);
                    int   oi = __shfl_xor_sync(0xffffffffu, li, o);
                    if (ov > lm || (ov == lm && oi < li)) { lm = ov; li = oi; }
                }
                if (lane == 0) { ssel[it] = lm; sv[li] = -CUDART_INF_F; }
                __syncwarp();
            }
        }
    } else if (wid == 1) {
        if (!s_fbbot) {
            float v = (lane < s_cbot) ? candB[lane] : CUDART_INF_F;
#pragma unroll
            for (int k = 2; k <= 32; k <<= 1) {
#pragma unroll
                for (int j = k >> 1; j > 0; j >>= 1) {
                    float o = __shfl_xor_sync(0xffffffffu, v, j);
                    bool up = ((lane & k) == 0);
                    bool keepMin = (((lane & j) == 0) == up);
                    v = keepMin ? fminf(v, o) : fmaxf(v, o);
                }
            }
            if (lane < 16) ssel[16 + lane] = v;    // ascending -> bottom-16 asc
        } else {
            for (int it = 0; it < TOPK; it++) {
                float lm = CUDART_INF_F; int li = 0;
                for (int j = lane; j < HW; j += 32) {
                    float v = sv2[j];
                    if (v < lm) { lm = v; li = j; }
                }
#pragma unroll
                for (int o = 16; o; o >>= 1) {
                    float ov = __shfl_xor_sync(0xffffffffu, lm, o);
                    int   oi = __shfl_xor_sync(0xffffffffu, li, o);
                    if (ov < lm || (ov == lm && oi < li)) { lm = ov; li = oi; }
                }
                if (lane == 0) { ssel[16 + it] = lm; sv2[li] = CUDART_INF_F; }
                __syncwarp();
            }
        }
    }

    // ALL warps: denominator, warp-uniform ascending traversal (LDS broadcast).
    // p_m = 2^(u*(m - mref)) in [0,1]; exact ex2 refresh at each group of 8.
    bool  pos  = (a >= 0.f);
    float u    = a * W;
    float mref = pos ? (float)(NB - 1) : 0.f;
    float cs   = fmaf(mref + 0.5f, W, lo);     // dominant bin center
    float L    = a * LN2F;
    float g1   = ex2(u);
    float g2   = g1 * g1;
    float g3   = g2 * g1;

    float D0 = 0.f, D1 = 0.f, D2 = 0.f, D3 = 0.f;
#pragma unroll
    for (int grp = 0; grp < NB; grp += 8) {
        float pr = ex2(u * ((float)grp - mref));
        float q0 = pr, q1 = pr * g1, q2 = pr * g2, q3 = pr * g3;
        float g4 = g2 * g2;
        float4 c0 = sbin[grp + 0];
        float4 c1 = sbin[grp + 1];
        float4 c2 = sbin[grp + 2];
        float4 c3 = sbin[grp + 3];
        D0 = fmaf(q0, fmaf(L, fmaf(L, fmaf(L, c0.w, c0.z), c0.y), c0.x), D0);
        D1 = fmaf(q1, fmaf(L, fmaf(L, fmaf(L, c1.w, c1.z), c1.y), c1.x), D1);
        D2 = fmaf(q2, fmaf(L, fmaf(L, fmaf(L, c2.w, c2.z), c2.y), c2.x), D2);
        D3 = fmaf(q3, fmaf(L, fmaf(L, fmaf(L, c3.w, c3.z), c3.y), c3.x), D3);
        q0 *= g4; q1 *= g4; q2 *= g4; q3 *= g4;
        float4 c4 = sbin[grp + 4];
        float4 c5 = sbin[grp + 5];
        float4 c6 = sbin[grp + 6];
        float4 c7 = sbin[grp + 7];
        D0 = fmaf(q0, fmaf(L, fmaf(L, fmaf(L, c4.w, c4.z), c4.y), c4.x), D0);
        D1 = fmaf(q1, fmaf(L, fmaf(L, fmaf(L, c5.w, c5.z), c5.y), c5.x), D1);
        D2 = fmaf(q2, fmaf(L, fmaf(L, fmaf(L, c6.w, c6.z), c6.y), c6.x), D2);
        D3 = fmaf(q3, fmaf(L, fmaf(L, fmaf(L, c7.w, c7.z), c7.y), c7.x), D3);
    }
    float Dref = (D0 + D1) + (D2 + D3);   // = sum exp2(a*bl_j - a*cs)

    __syncthreads();   // ssel ready

    float nm = -a * cs;
    float rD = __frcp_rn(Dref);
    const float* sel = pos ? ssel : (ssel + 16);
    float v[TOPK];
#pragma unroll
    for (int k = 0; k < TOPK; k++)
        v[k] = ex2(fmaf(a, sel[k], nm)) * rD;

    // output: idx = i*16 + k ; k2 = i/44 (k-independent)
    int i  = tid;
    int n  = r / (S_FR - 1);
    int sp = r - n * (S_FR - 1);
    int k2 = i / 44;
    int im = i - k2 * 44;
    float4* o = reinterpret_cast<float4*>(
        out + ((size_t)((n * TOPK + k2) * (S_FR - 1) + sp)) * HW + im * 16);
    o[0] = make_float4(v[0],  v[1],  v[2],  v[3]);
    o[1] = make_float4(v[4],  v[5],  v[6],  v[7]);
    o[2] = make_float4(v[8],  v[9],  v[10], v[11]);
    o[3] = make_float4(v[12], v[13], v[14], v[15]);
}

// ---------------------------------------------------------------------------
extern "C" void kernel_launch(void* const* d_in, const int* in_sizes, int n_in,
                              void* d_out, int out_size) {
    const float* x  = (const float*)d_in[0];
    const float* w1 = (const float*)d_in[1];
    const float* b1 = (const float*)d_in[2];
    const float* w2 = (const float*)d_in[3];
    const float* b2 = (const float*)d_in[4];
    float* out = (float*)d_out;

    kA<<<NPIX / 64, 128>>>(x, w1, b1, w2, b2);
    kBC<<<NS, HW>>>(out);
}

// round 10
// speedup vs baseline: 1.1783x; 1.1783x over previous
#include <cuda_runtime.h>
#include <math_constants.h>

// Problem constants
#define N_BATCH 4
#define C_CH    128
#define S_FR    31
#define HW      704           // 32*22
#define NS      120           // 4*(31-1)
#define NPIX    87296         // 4*31*704 (= 64*1364)
#define TOPK    16
#define NB      64            // denominator bins
#define NWARP   22            // 704/32
#define LOG2E   1.4426950408889634f
#define LN2F    0.6931471805599453f

// Scratch (device globals — no allocation allowed)
__device__ float  g_X0[NS * HW];        // a values
__device__ float  g_BL[NS * HW];        // b * log2e (order-preserving)
__device__ float  g_TB[NS * 32];        // [0..15] top desc, [16..31] bottom asc
__device__ float4 g_BINS[NS * NB];      // (S0, S1, S2/2, S3/6)
__device__ float2 g_ROW[NS];            // (lo, W)

__device__ __forceinline__ float ex2(float x) {
    float r;
    asm("ex2.approx.f32 %0, %1;" : "=f"(r) : "f"(x));
    return r;
}

// ---------------------------------------------------------------------------
// Kernel A (R3 winner, verbatim): channel contraction, 2 threads per pixel.
// ---------------------------------------------------------------------------
__global__ void kA(const float* __restrict__ x,
                   const float* __restrict__ w1, const float* __restrict__ b1,
                   const float* __restrict__ w2, const float* __restrict__ b2) {
    __shared__ float sw1[C_CH], sw2[C_CH];
    __shared__ float r1s[64], r2s[64];
    int tid = threadIdx.x;          // 0..127
    sw1[tid] = w1[tid];
    sw2[tid] = w2[tid];
    __syncthreads();

    int half = tid >> 6;            // 0 or 1
    int px   = tid & 63;
    int p = blockIdx.x * 64 + px;   // NPIX = 64*1364 exactly
    int n = p / (S_FR * HW);
    int q = p - n * (S_FR * HW);
    int f = q / HW;
    int i = q - f * HW;

    const float* xp = x + (size_t)n * (C_CH * S_FR * HW)
                        + (size_t)(half * 64) * (S_FR * HW) + q;
    const float* pw1 = sw1 + half * 64;
    const float* pw2 = sw2 + half * 64;

    float y1a = 0.f, y1b = 0.f, y2a = 0.f, y2b = 0.f;
#pragma unroll
    for (int cb = 0; cb < 64; cb += 16) {
        float v[16];
#pragma unroll
        for (int u = 0; u < 16; u++) v[u] = xp[(cb + u) * (S_FR * HW)];
#pragma unroll
        for (int u = 0; u < 16; u += 2) {
            y1a = fmaf(v[u],     pw1[cb + u],     y1a);
            y2a = fmaf(v[u],     pw2[cb + u],     y2a);
            y1b = fmaf(v[u + 1], pw1[cb + u + 1], y1b);
            y2b = fmaf(v[u + 1], pw2[cb + u + 1], y2b);
        }
    }
    float y1 = y1a + y1b, y2 = y2a + y2b;

    if (half == 1) { r1s[px] = y1; r2s[px] = y2; }
    __syncthreads();
    if (half == 0) {
        y1 += r1s[px];
        y2 += r2s[px];
        if (f < S_FR - 1) g_X0[(n * (S_FR - 1) + f) * HW + i] = y1 + b1[0];
        if (f >= 1)       g_BL[(n * (S_FR - 1) + f - 1) * HW + i] = (y2 + b2[0]) * LOG2E;
    }
}

// ---------------------------------------------------------------------------
// Kernel B: per-row summary only (short critical path).
// min/max -> NB=64 moment bins (separate arrays, bank-spread atomics) ->
// histogram thresholds -> candidate gather + warp bitonic (fallback iter).
// Writes g_TB, g_BINS, g_ROW.
// ---------------------------------------------------------------------------
__global__ void __launch_bounds__(HW)
kB() {
    __shared__ float sv[HW], sv2[HW];
    __shared__ float binS0[NB], binS1[NB], binS2[NB], binS3[NB];
    __shared__ float rmin[NWARP], rmax[NWARP];
    __shared__ float s_lo, s_W;
    __shared__ int   s_ttop, s_tbot, s_fbtop, s_fbbot;
    __shared__ int   s_ctop, s_cbot;
    __shared__ float candT[40], candB[40];

    int r = blockIdx.x;
    int tid = threadIdx.x;   // 0..703
    int lane = tid & 31, wid = tid >> 5;

    float bv = g_BL[r * HW + tid];
    sv[tid] = bv; sv2[tid] = bv;
    if (tid < NB) { binS0[tid] = 0.f; binS1[tid] = 0.f; binS2[tid] = 0.f; binS3[tid] = 0.f; }
    if (tid == HW - 1) { s_ctop = 0; s_cbot = 0; }

    float lmin = bv, lmax = bv;
#pragma unroll
    for (int o = 16; o; o >>= 1) {
        lmin = fminf(lmin, __shfl_xor_sync(0xffffffffu, lmin, o));
        lmax = fmaxf(lmax, __shfl_xor_sync(0xffffffffu, lmax, o));
    }
    if (lane == 0) { rmin[wid] = lmin; rmax[wid] = lmax; }
    __syncthreads();
    if (tid == 0) {
        float lo = rmin[0], hi = rmax[0];
#pragma unroll
        for (int w = 1; w < NWARP; w++) { lo = fminf(lo, rmin[w]); hi = fmaxf(hi, rmax[w]); }
        s_lo = lo;
        s_W  = (hi - lo) * (1.0f / NB) + 1e-30f;
        g_ROW[r] = make_float2(lo, s_W);
    }
    __syncthreads();

    float lo = s_lo, W = s_W, invW = 1.0f / W;
    int m;
    {
        m = (int)((bv - lo) * invW);
        m = (m > NB - 1) ? NB - 1 : (m < 0 ? 0 : m);
        float d = bv - fmaf((float)m + 0.5f, W, lo);
        atomicAdd(&binS0[m], 1.0f);
        atomicAdd(&binS1[m], d);
        atomicAdd(&binS2[m], 0.5f * d * d);
        atomicAdd(&binS3[m], (1.0f / 6.0f) * d * d * d);
    }
    __syncthreads();

    // thresholds (lane owns bins 2l, 2l+1)
    if (wid == 0) {
        float c0 = binS0[2 * lane];
        float c1 = binS0[2 * lane + 1];
        float suf = c0 + c1;
#pragma unroll
        for (int o = 1; o < 32; o <<= 1) {
            float v = __shfl_down_sync(0xffffffffu, suf, o);
            if (lane + o < 32) suf += v;
        }
        float Seven = suf;              // suffix from bin 2l
        float Sodd  = suf - c0;         // suffix from bin 2l+1
        int best = -1;
        if (Sodd  >= 16.f) best = 2 * lane + 1;
        else if (Seven >= 16.f) best = 2 * lane;
        float Sb = (best == 2 * lane + 1) ? Sodd : ((best == 2 * lane) ? Seven : 0.f);
#pragma unroll
        for (int o = 16; o; o >>= 1) {
            int   ob = __shfl_xor_sync(0xffffffffu, best, o);
            float os = __shfl_xor_sync(0xffffffffu, Sb, o);
            if (ob > best) { best = ob; Sb = os; }
        }
        if (lane == 0) { s_ttop = best; s_fbtop = (Sb > 32.f) ? 1 : 0; }
    } else if (wid == 1) {
        float c0 = binS0[2 * lane];
        float c1 = binS0[2 * lane + 1];
        float pre = c0 + c1;
#pragma unroll
        for (int o = 1; o < 32; o <<= 1) {
            float v = __shfl_up_sync(0xffffffffu, pre, o);
            if (lane >= o) pre += v;
        }
        float Podd  = pre;              // prefix through bin 2l+1
        float Peven = pre - c1;         // prefix through bin 2l
        int best = 0x7fffffff;
        if (Peven >= 16.f) best = 2 * lane;
        else if (Podd >= 16.f) best = 2 * lane + 1;
        float Pb = (best == 2 * lane) ? Peven : ((best == 2 * lane + 1) ? Podd : 0.f);
#pragma unroll
        for (int o = 16; o; o >>= 1) {
            int   ob = __shfl_xor_sync(0xffffffffu, best, o);
            float os = __shfl_xor_sync(0xffffffffu, Pb, o);
            if (ob < best) { best = ob; Pb = os; }
        }
        if (lane == 0) { s_tbot = best; s_fbbot = (Pb > 32.f) ? 1 : 0; }
    }
    __syncthreads();

    if (!s_fbtop && m >= s_ttop) candT[atomicAdd(&s_ctop, 1)] = bv;
    if (!s_fbbot && m <= s_tbot) candB[atomicAdd(&s_cbot, 1)] = bv;
    // write bins while gather settles
    if (tid < NB)
        g_BINS[r * NB + tid] = make_float4(binS0[tid], binS1[tid], binS2[tid], binS3[tid]);
    __syncthreads();

    if (wid == 0) {
        if (!s_fbtop) {
            float v = (lane < s_ctop) ? candT[lane] : -CUDART_INF_F;
#pragma unroll
            for (int k = 2; k <= 32; k <<= 1) {
#pragma unroll
                for (int j = k >> 1; j > 0; j >>= 1) {
                    float o = __shfl_xor_sync(0xffffffffu, v, j);
                    bool up = ((lane & k) == 0);
                    bool keepMin = (((lane & j) == 0) == up);
                    v = keepMin ? fminf(v, o) : fmaxf(v, o);
                }
            }
            if (lane >= 16) g_TB[r * 32 + (31 - lane)] = v;   // top-16 desc
        } else {
            for (int it = 0; it < TOPK; it++) {
                float lm = -CUDART_INF_F; int li = 0;
                for (int j = lane; j < HW; j += 32) {
                    float v = sv[j];
                    if (v > lm) { lm = v; li = j; }
                }
#pragma unroll
                for (int o = 16; o; o >>= 1) {
                    float ov = __shfl_xor_sync(0xffffffffu, lm, o);
                    int   oi = __shfl_xor_sync(0xffffffffu, li, o);
                    if (ov > lm || (ov == lm && oi < li)) { lm = ov; li = oi; }
                }
                if (lane == 0) { g_TB[r * 32 + it] = lm; sv[li] = -CUDART_INF_F; }
                __syncwarp();
            }
        }
    } else if (wid == 1) {
        if (!s_fbbot) {
            float v = (lane < s_cbot) ? candB[lane] : CUDART_INF_F;
#pragma unroll
            for (int k = 2; k <= 32; k <<= 1) {
#pragma unroll
                for (int j = k >> 1; j > 0; j >>= 1) {
                    float o = __shfl_xor_sync(0xffffffffu, v, j);
                    bool up = ((lane & k) == 0);
                    bool keepMin = (((lane & j) == 0) == up);
                    v = keepMin ? fminf(v, o) : fmaxf(v, o);
                }
            }
            if (lane < 16) g_TB[r * 32 + 16 + lane] = v;      // bottom-16 asc
        } else {
            for (int it = 0; it < TOPK; it++) {
                float lm = CUDART_INF_F; int li = 0;
                for (int j = lane; j < HW; j += 32) {
                    float v = sv2[j];
                    if (v < lm) { lm = v; li = j; }
                }
#pragma unroll
                for (int o = 16; o; o >>= 1) {
                    float ov = __shfl_xor_sync(0xffffffffu, lm, o);
                    int   oi = __shfl_xor_sync(0xffffffffu, li, o);
                    if (ov < lm || (ov == lm && oi < li)) { lm = ov; li = oi; }
                }
                if (lane == 0) { g_TB[r * 32 + 16 + it] = lm; sv2[li] = CUDART_INF_F; }
                __syncwarp();
            }
        }
    }
}

// ---------------------------------------------------------------------------
// Kernel C: wide barrier-free emit. 1320 blocks x 64 threads; one smem fill,
// then each thread independent: uniform-ascending bin chain (exact ex2
// refresh per 8 bins) + 16 numerators + 4x STG.128.
// ---------------------------------------------------------------------------
__global__ void __launch_bounds__(64)
kC(float* __restrict__ out) {
    __shared__ float4 sb[NB];
    __shared__ float  ssel[32];
    __shared__ float2 srow;
    int r = blockIdx.x / 11;
    int chunk = blockIdx.x - r * 11;
    int tid = threadIdx.x;   // 64

    sb[tid] = g_BINS[r * NB + tid];
    if (tid < 32) ssel[tid] = g_TB[r * 32 + tid];
    if (tid == 63) srow = g_ROW[r];
    __syncthreads();

    int i = chunk * 64 + tid;
    float a  = g_X0[r * HW + i];
    float lo = srow.x, W = srow.y;

    bool  pos  = (a >= 0.f);
    float u    = a * W;
    float mref = pos ? (float)(NB - 1) : 0.f;
    float cs   = fmaf(mref + 0.5f, W, lo);     // dominant bin center
    float L    = a * LN2F;
    float g1   = ex2(u);
    float g2   = g1 * g1;
    float g3   = g2 * g1;
    float g4   = g2 * g2;

    float D0 = 0.f, D1 = 0.f, D2 = 0.f, D3 = 0.f;
#pragma unroll
    for (int grp = 0; grp < NB; grp += 8) {
        float pr = ex2(u * ((float)grp - mref));
        float q0 = pr, q1 = pr * g1, q2 = pr * g2, q3 = pr * g3;
        float4 c0 = sb[grp + 0];
        float4 c1 = sb[grp + 1];
        float4 c2 = sb[grp + 2];
        float4 c3 = sb[grp + 3];
        D0 = fmaf(q0, fmaf(L, fmaf(L, fmaf(L, c0.w, c0.z), c0.y), c0.x), D0);
        D1 = fmaf(q1, fmaf(L, fmaf(L, fmaf(L, c1.w, c1.z), c1.y), c1.x), D1);
        D2 = fmaf(q2, fmaf(L, fmaf(L, fmaf(L, c2.w, c2.z), c2.y), c2.x), D2);
        D3 = fmaf(q3, fmaf(L, fmaf(L, fmaf(L, c3.w, c3.z), c3.y), c3.x), D3);
        q0 *= g4; q1 *= g4; q2 *= g4; q3 *= g4;
        float4 c4 = sb[grp + 4];
        float4 c5 = sb[grp + 5];
        float4 c6 = sb[grp + 6];
        float4 c7 = sb[grp + 7];
        D0 = fmaf(q0, fmaf(L, fmaf(L, fmaf(L, c4.w, c4.z), c4.y), c4.x), D0);
        D1 = fmaf(q1, fmaf(L, fmaf(L, fmaf(L, c5.w, c5.z), c5.y), c5.x), D1);
        D2 = fmaf(q2, fmaf(L, fmaf(L, fmaf(L, c6.w, c6.z), c6.y), c6.x), D2);
        D3 = fmaf(q3, fmaf(L, fmaf(L, fmaf(L, c7.w, c7.z), c7.y), c7.x), D3);
    }
    float Dref = (D0 + D1) + (D2 + D3);   // = sum exp2(a*bl_j - a*cs)

    float nm = -a * cs;
    float rD = __frcp_rn(Dref);
    const float* sel = pos ? ssel : (ssel + 16);
    float v[TOPK];
#pragma unroll
    for (int k = 0; k < TOPK; k++)
        v[k] = ex2(fmaf(a, sel[k], nm)) * rD;

    // output: idx = i*16 + k ; k2 = i/44 (k-independent)
    int n  = r / (S_FR - 1);
    int sp = r - n * (S_FR - 1);
    int k2 = i / 44;
    int im = i - k2 * 44;
    float4* o = reinterpret_cast<float4*>(
        out + ((size_t)((n * TOPK + k2) * (S_FR - 1) + sp)) * HW + im * 16);
    o[0] = make_float4(v[0],  v[1],  v[2],  v[3]);
    o[1] = make_float4(v[4],  v[5],  v[6],  v[7]);
    o[2] = make_float4(v[8],  v[9],  v[10], v[11]);
    o[3] = make_float4(v[12], v[13], v[14], v[15]);
}

// ---------------------------------------------------------------------------
extern "C" void kernel_launch(void* const* d_in, const int* in_sizes, int n_in,
                              void* d_out, int out_size) {
    const float* x  = (const float*)d_in[0];
    const float* w1 = (const float*)d_in[1];
    const float* b1 = (const float*)d_in[2];
    const float* w2 = (const float*)d_in[3];
    const float* b2 = (const float*)d_in[4];
    float* out = (float*)d_out;

    kA<<<NPIX / 64, 128>>>(x, w1, b1, w2, b2);
    kB<<<NS, HW>>>();
    kC<<<NS * 11, 64>>>(out);
}